// round 2
// baseline (speedup 1.0000x reference)
#include <cuda_runtime.h>
#include <math.h>

#define Bn 4
#define Tn 1024
#define Sn 64
#define En 128
#define NHn 4
#define DHn 32
#define FFn 256
#define Ln 3
#define Cn 4
#define SX 132            // padded row stride for 64x128 tiles
#define SF 260            // padded row stride for 64x256 FF tile
#define NTHREADS 256

typedef unsigned long long ull;

// ---- packed f32x2 helpers (Blackwell sm_103a) ----
__device__ __forceinline__ ull pk2(float lo, float hi){
    ull r; asm("mov.b64 %0, {%1,%2};" : "=l"(r) : "f"(lo), "f"(hi)); return r;
}
__device__ __forceinline__ void upk2(ull p, float& lo, float& hi){
    asm("mov.b64 {%0,%1}, %2;" : "=f"(lo), "=f"(hi) : "l"(p));
}
__device__ __forceinline__ ull fma2(ull a, ull b, ull c){
    ull d; asm("fma.rn.f32x2 %0, %1, %2, %3;" : "=l"(d) : "l"(a), "l"(b), "l"(c)); return d;
}

__device__ __forceinline__ float gelu_tanh(float x){
    float x3 = x*x*x;
    float t = tanhf(0.7978845608028654f*(x + 0.044715f*x3));
    return 0.5f*x*(1.0f + t);
}

// ---- layernorm: 4 threads per row, stride-4 element mapping (conflict-free) ----
__device__ __forceinline__ void layernorm(const float* __restrict__ src,
        float* __restrict__ dst, const float* __restrict__ g, const float* __restrict__ b)
{
    const int t   = threadIdx.x;
    const int row = t >> 2;
    const int q4  = t & 3;
    const float* xr = src + row*SX;
    float s = 0.f, s2 = 0.f;
    #pragma unroll
    for (int i = 0; i < 32; i++){
        float v = xr[q4 + 4*i];
        s += v; s2 = fmaf(v, v, s2);
    }
    s  += __shfl_xor_sync(0xffffffffu, s, 1);
    s2 += __shfl_xor_sync(0xffffffffu, s2, 1);
    s  += __shfl_xor_sync(0xffffffffu, s, 2);
    s2 += __shfl_xor_sync(0xffffffffu, s2, 2);
    const float m    = s * 0.0078125f;
    const float rstd = rsqrtf(s2*0.0078125f - m*m + 1e-5f);
    float* dr = dst + row*SX;
    #pragma unroll
    for (int i = 0; i < 32; i++){
        int c = q4 + 4*i;
        dr[c] = (xr[c] - m)*rstd*g[c] + b[c];
    }
}

// ---- GEMM: out[64,OC] = src[64,IC] @ W[IC,OC] + bias ; MODE 0=store 1=residual-into-dst 2=gelu
// warp w -> rows 8w..8w+7 ; lane -> 4 cols (f32x2 pairs). W read from L2/L1 (coalesced float4).
template<int IC, int OC, int SHI, int SHO, int MODE>
__device__ __forceinline__ void gemm(const float* __restrict__ src,
                                     const float* __restrict__ W,
                                     const float* __restrict__ bias,
                                     float* __restrict__ dst)
{
    const int warp = threadIdx.x >> 5;
    const int lane = threadIdx.x & 31;
    const int row0 = warp << 3;
    #pragma unroll
    for (int cg = 0; cg < OC/128; ++cg){
        const int col = cg*128 + lane*4;
        ull acc0[8], acc1[8];
        {
            const float4 bb = *(const float4*)(bias + col);
            const ull i0 = pk2(bb.x, bb.y), i1 = pk2(bb.z, bb.w);
            #pragma unroll
            for (int r = 0; r < 8; r++){ acc0[r] = i0; acc1[r] = i1; }
        }
        #pragma unroll 2
        for (int kk = 0; kk < IC; kk += 4){
            float4 h4[8];
            #pragma unroll
            for (int r = 0; r < 8; r++)
                h4[r] = *(const float4*)(src + (row0 + r)*SHI + kk);
            #pragma unroll
            for (int u = 0; u < 4; u++){
                const float4 wv = __ldg((const float4*)(W + (kk + u)*OC + col));
                const ull w01 = pk2(wv.x, wv.y);
                const ull w23 = pk2(wv.z, wv.w);
                #pragma unroll
                for (int r = 0; r < 8; r++){
                    const float h = (u==0) ? h4[r].x : (u==1) ? h4[r].y
                                  : (u==2) ? h4[r].z : h4[r].w;
                    const ull hp = pk2(h, h);
                    acc0[r] = fma2(hp, w01, acc0[r]);
                    acc1[r] = fma2(hp, w23, acc1[r]);
                }
            }
        }
        #pragma unroll
        for (int r = 0; r < 8; r++){
            float o0, o1, o2, o3;
            upk2(acc0[r], o0, o1); upk2(acc1[r], o2, o3);
            float* dp = dst + (row0 + r)*SHO + col;
            if (MODE == 1){
                float4 xv = *(const float4*)dp;
                o0 += xv.x; o1 += xv.y; o2 += xv.z; o3 += xv.w;
            } else if (MODE == 2){
                o0 = gelu_tanh(o0); o1 = gelu_tanh(o1);
                o2 = gelu_tanh(o2); o3 = gelu_tanh(o3);
            }
            *(float4*)dp = make_float4(o0, o1, o2, o3);
        }
    }
}

// ---- attention: thread = (head, row); 64 scores in registers; masked keys skipped ----
__device__ __forceinline__ void attention(const float* __restrict__ Qb,
        const float* __restrict__ Kb, const float* __restrict__ Vb,
        float* __restrict__ Ob, int valid)
{
    const int t    = threadIdx.x;
    const int head = t >> 6;
    const int row  = t & 63;
    const int base = head * DHn;
    const float scale = 0.17677669529663687f; // 1/sqrt(32)

    float4 qv[8];
    #pragma unroll
    for (int j4 = 0; j4 < 8; j4++)
        qv[j4] = *(const float4*)(Qb + row*SX + base + j4*4);

    float s[64];
    #pragma unroll
    for (int tt = 0; tt < 64; ++tt){
        float acc = 0.f;
        if (tt < valid){
            const float4* kp = (const float4*)(Kb + tt*SX + base);
            #pragma unroll
            for (int j4 = 0; j4 < 8; j4++){
                float4 kv = kp[j4];
                acc = fmaf(qv[j4].x, kv.x, acc);
                acc = fmaf(qv[j4].y, kv.y, acc);
                acc = fmaf(qv[j4].z, kv.z, acc);
                acc = fmaf(qv[j4].w, kv.w, acc);
            }
        }
        s[tt] = acc * scale;
    }
    float m = -1e30f;
    #pragma unroll
    for (int tt = 0; tt < 64; ++tt) if (tt < valid) m = fmaxf(m, s[tt]);
    float sum = 0.f;
    #pragma unroll
    for (int tt = 0; tt < 64; ++tt){
        float e = (tt < valid) ? __expf(s[tt] - m) : 0.f;
        s[tt] = e; sum += e;
    }
    float4 ov[8];
    #pragma unroll
    for (int j4 = 0; j4 < 8; j4++) ov[j4] = make_float4(0.f, 0.f, 0.f, 0.f);
    #pragma unroll
    for (int tt = 0; tt < 64; ++tt){
        if (tt < valid){
            const float a = s[tt];
            const float4* vp = (const float4*)(Vb + tt*SX + base);
            #pragma unroll
            for (int j4 = 0; j4 < 8; j4++){
                float4 vv = vp[j4];
                ov[j4].x = fmaf(a, vv.x, ov[j4].x);
                ov[j4].y = fmaf(a, vv.y, ov[j4].y);
                ov[j4].z = fmaf(a, vv.z, ov[j4].z);
                ov[j4].w = fmaf(a, vv.w, ov[j4].w);
            }
        }
    }
    const float inv = 1.0f / sum;
    #pragma unroll
    for (int j4 = 0; j4 < 8; j4++){
        float4 o = ov[j4];
        o.x *= inv; o.y *= inv; o.z *= inv; o.w *= inv;
        *(float4*)(Ob + row*SX + base + j4*4) = o;
    }
}

#define SMEM_FLOATS (5*Sn*SX + 2*Sn*16)
#define SMEM_BYTES  (SMEM_FLOATS*4)

__global__ void __launch_bounds__(NTHREADS, 1) rowinteraction_kernel(
    const float* __restrict__ emb,  const float* __restrict__ cls,
    const float* __restrict__ ln1g, const float* __restrict__ ln1b,
    const float* __restrict__ wq,   const float* __restrict__ bq,
    const float* __restrict__ wk,   const float* __restrict__ bk,
    const float* __restrict__ wv,   const float* __restrict__ bv,
    const float* __restrict__ wo,   const float* __restrict__ bo,
    const float* __restrict__ ln2g, const float* __restrict__ ln2b,
    const float* __restrict__ w1,   const float* __restrict__ b1,
    const float* __restrict__ w2,   const float* __restrict__ b2,
    const float* __restrict__ og,   const float* __restrict__ ob,
    const int*   __restrict__ dvec, float* __restrict__ out)
{
    extern __shared__ float smf[];
    float* X   = smf;                 // [64][132]  residual stream
    float* A   = X  + Sn*SX;          // [64][132]  ln-out / attn-out scratch
    float* Qb  = A  + Sn*SX;
    float* Kb  = Qb + Sn*SX;
    float* Vb  = Kb + Sn*SX;
    float* FFb = Qb;                  // [64][260] overlays Q+K (16640 <= 16896 floats)
    float* RC  = Vb + Sn*SX;          // rope cos [64][16]
    float* RS  = RC + Sn*16;          // rope sin [64][16]

    const int tid   = threadIdx.x;
    const int n     = blockIdx.x;
    const int bidx  = n >> 10;        // T = 1024
    const int valid = dvec[bidx] + Cn;

    // RoPE tables (same for all layers)
    for (int idx = tid; idx < Sn*16; idx += NTHREADS){
        int pos = idx >> 4, f = idx & 15;
        float inv = expf(-((float)(2*f) / (float)DHn) * logf(100000.0f));
        float ang = (float)pos * inv;
        RC[idx] = cosf(ang); RS[idx] = sinf(ang);
    }
    // Load residual stream: rows 0..3 = cls tokens, rows 4..63 = embeddings
    for (int idx = tid; idx < Sn*En; idx += NTHREADS){
        int r = idx >> 7, c = idx & 127;
        float v = (r < Cn) ? cls[r*En + c] : emb[((size_t)n*Sn + r)*En + c];
        X[r*SX + c] = v;
    }
    __syncthreads();

    for (int l = 0; l < Ln; ++l){
        layernorm(X, A, ln1g + l*En, ln1b + l*En);
        __syncthreads();
        gemm<En, En, SX, SX, 0>(A, wq + l*En*En, bq + l*En, Qb);
        gemm<En, En, SX, SX, 0>(A, wk + l*En*En, bk + l*En, Kb);
        gemm<En, En, SX, SX, 0>(A, wv + l*En*En, bv + l*En, Vb);
        __syncthreads();
        // RoPE on q,k in place: idx -> (row, head, j<16)
        for (int idx = tid; idx < Sn*NHn*16; idx += NTHREADS){
            int row = idx >> 6; int hj = idx & 63; int h = hj >> 4; int j = hj & 15;
            float cc = RC[row*16 + j], ss = RS[row*16 + j];
            int o1 = row*SX + h*DHn + j, o2 = o1 + 16;
            float q1 = Qb[o1], q2 = Qb[o2];
            Qb[o1] = q1*cc - q2*ss;  Qb[o2] = q2*cc + q1*ss;
            float k1 = Kb[o1], k2 = Kb[o2];
            Kb[o1] = k1*cc - k2*ss;  Kb[o2] = k2*cc + k1*ss;
        }
        __syncthreads();
        attention(Qb, Kb, Vb, A, valid);
        __syncthreads();
        gemm<En, En, SX, SX, 1>(A, wo + l*En*En, bo + l*En, X);   // x += o @ wo + bo
        __syncthreads();
        layernorm(X, A, ln2g + l*En, ln2b + l*En);
        __syncthreads();
        gemm<En, FFn, SX, SF, 2>(A, w1 + l*En*FFn, b1 + l*FFn, FFb);  // gelu(h2@w1+b1)
        __syncthreads();
        gemm<FFn, En, SF, SX, 1>(FFb, w2 + l*FFn*En, b2 + l*En, X);   // x += ff@w2+b2
        __syncthreads();
    }

    // Epilogue: layernorm rows 0..3 with out_ln, write (B,T,C*E)
    const int warp = tid >> 5, lane = tid & 31;
    if (warp < Cn){
        const float4 xv = *(const float4*)(X + warp*SX + lane*4);
        float s  = xv.x + xv.y + xv.z + xv.w;
        float s2 = xv.x*xv.x + xv.y*xv.y + xv.z*xv.z + xv.w*xv.w;
        #pragma unroll
        for (int o = 16; o; o >>= 1){
            s  += __shfl_xor_sync(0xffffffffu, s,  o);
            s2 += __shfl_xor_sync(0xffffffffu, s2, o);
        }
        const float m    = s * 0.0078125f;
        const float rstd = rsqrtf(s2*0.0078125f - m*m + 1e-5f);
        const float4 gv  = *(const float4*)(og + lane*4);
        const float4 bv4 = *(const float4*)(ob + lane*4);
        float4 ovv;
        ovv.x = (xv.x - m)*rstd*gv.x + bv4.x;
        ovv.y = (xv.y - m)*rstd*gv.y + bv4.y;
        ovv.z = (xv.z - m)*rstd*gv.z + bv4.z;
        ovv.w = (xv.w - m)*rstd*gv.w + bv4.w;
        *(float4*)(out + (size_t)n*(Cn*En) + warp*En + lane*4) = ovv;
    }
}

extern "C" void kernel_launch(void* const* d_in, const int* in_sizes, int n_in,
                              void* d_out, int out_size)
{
    (void)in_sizes; (void)n_in; (void)out_size;
    cudaFuncSetAttribute(rowinteraction_kernel,
                         cudaFuncAttributeMaxDynamicSharedMemorySize, SMEM_BYTES);
    rowinteraction_kernel<<<Bn*Tn, NTHREADS, SMEM_BYTES>>>(
        (const float*)d_in[0],  (const float*)d_in[1],
        (const float*)d_in[2],  (const float*)d_in[3],
        (const float*)d_in[4],  (const float*)d_in[5],
        (const float*)d_in[6],  (const float*)d_in[7],
        (const float*)d_in[8],  (const float*)d_in[9],
        (const float*)d_in[10], (const float*)d_in[11],
        (const float*)d_in[12], (const float*)d_in[13],
        (const float*)d_in[14], (const float*)d_in[15],
        (const float*)d_in[16], (const float*)d_in[17],
        (const float*)d_in[18], (const float*)d_in[19],
        (const int*)d_in[20],   (float*)d_out);
}

// round 3
// speedup vs baseline: 1.3176x; 1.3176x over previous
#include <cuda_runtime.h>
#include <math.h>

#define Bn 4
#define Tn 1024
#define Sn 64
#define En 128
#define NHn 4
#define DHn 32
#define FFn 256
#define Ln 3
#define Cn 4
#define SX 132            // row-major stride (floats)
#define STR 66            // transposed (k-major) stride — even => 8B-aligned row pairs
#define NTHREADS 256

typedef unsigned long long ull;

// ---- packed f32x2 helpers (sm_103a) ----
__device__ __forceinline__ ull pk2(float lo, float hi){
    ull r; asm("mov.b64 %0, {%1,%2};" : "=l"(r) : "f"(lo), "f"(hi)); return r;
}
__device__ __forceinline__ void upk2(ull p, float& lo, float& hi){
    asm("mov.b64 {%0,%1}, %2;" : "=f"(lo), "=f"(hi) : "l"(p));
}
__device__ __forceinline__ ull fma2(ull a, ull b, ull c){
    ull d; asm("fma.rn.f32x2 %0, %1, %2, %3;" : "=l"(d) : "l"(a), "l"(b), "l"(c)); return d;
}

__device__ __forceinline__ float gelu_tanh(float x){
    float x3 = x*x*x;
    float t = tanhf(0.7978845608028654f*(x + 0.044715f*x3));
    return 0.5f*x*(1.0f + t);
}

// ---- layernorm: src row-major X, dst TRANSPOSED HT[c][row]; skips rows >= valid ----
__device__ __forceinline__ void layernorm_t(const float* __restrict__ src,
        float* __restrict__ dstT, const float* __restrict__ g,
        const float* __restrict__ b, int valid)
{
    const int t   = threadIdx.x;
    const int row = t >> 2;
    const int q4  = t & 3;
    if (row < valid){
        const unsigned gmask = 0xFu << ((t & 31) & ~3);  // 4-lane row group
        const float* xr = src + row*SX;
        float s = 0.f, s2 = 0.f;
        #pragma unroll
        for (int i = 0; i < 32; i++){
            float v = xr[q4 + 4*i];
            s += v; s2 = fmaf(v, v, s2);
        }
        s  += __shfl_xor_sync(gmask, s, 1);
        s2 += __shfl_xor_sync(gmask, s2, 1);
        s  += __shfl_xor_sync(gmask, s, 2);
        s2 += __shfl_xor_sync(gmask, s2, 2);
        const float m    = s * 0.0078125f;
        const float rstd = rsqrtf(s2*0.0078125f - m*m + 1e-5f);
        #pragma unroll
        for (int i = 0; i < 32; i++){
            int c = q4 + 4*i;
            dstT[c*STR + row] = (xr[c] - m)*rstd*g[c] + b[c];
        }
    }
}

// ---- GEMM: dst[r][c] = sum_k srcT[k][r] * W[k][c] + bias[c]
// srcT is k-major (stride STR). Work unit = 8 rows x 64 cols; units round-robin
// over 8 warps so reduced row count (nrb row-blocks) speeds the whole CTA.
// Per lane: 2 cols; rows as 4 f32x2 pairs loaded straight from srcT.
// MODE 0 = store row-major; 1 = add into row-major dst; 2 = gelu, store TRANSPOSED.
template<int IC, int OC, int MODE>
__device__ __forceinline__ void gemm_t(const float* __restrict__ srcT,
                                       const float* __restrict__ W,
                                       const float* __restrict__ bias,
                                       float* __restrict__ dst, int nrb)
{
    const int warp = threadIdx.x >> 5;
    const int lane = threadIdx.x & 31;
    const int NCH  = OC / 64;
    const int nunits = nrb * NCH;
    for (int u = warp; u < nunits; u += 8){
        const int rb = u / NCH;          // NCH is 2 or 4 -> shift
        const int ch = u - rb*NCH;
        const int r0 = rb << 3;
        const int c0 = ch*64 + lane*2;
        const float* Wp = W + c0;

        ull acc[4][2];
        {
            const float2 bb = *(const float2*)(bias + c0);
            const ull b0 = pk2(bb.x, bb.x), b1 = pk2(bb.y, bb.y);
            #pragma unroll
            for (int p = 0; p < 4; p++){ acc[p][0] = b0; acc[p][1] = b1; }
        }
        float2 wr[4];
        #pragma unroll
        for (int j = 0; j < 4; j++) wr[j] = __ldg((const float2*)(Wp + j*OC));

        #pragma unroll 1
        for (int kk = 0; kk < IC; kk += 4){
            const int kn = (kk + 4 < IC) ? (kk + 4) : kk;   // prefetch next k-group
            float2 wn[4];
            #pragma unroll
            for (int j = 0; j < 4; j++) wn[j] = __ldg((const float2*)(Wp + (kn + j)*OC));
            #pragma unroll
            for (int j = 0; j < 4; j++){
                const ull* hp = (const ull*)(srcT + (kk + j)*STR + r0); // row pairs
                const ull w0 = pk2(wr[j].x, wr[j].x);
                const ull w1 = pk2(wr[j].y, wr[j].y);
                #pragma unroll
                for (int p = 0; p < 4; p++){
                    const ull h = hp[p];
                    acc[p][0] = fma2(h, w0, acc[p][0]);
                    acc[p][1] = fma2(h, w1, acc[p][1]);
                }
            }
            #pragma unroll
            for (int j = 0; j < 4; j++) wr[j] = wn[j];
        }
        #pragma unroll
        for (int p = 0; p < 4; p++){
            float a0, a1, c1r0, c1r1;
            upk2(acc[p][0], a0, a1);      // col c0:   rows r, r+1
            upk2(acc[p][1], c1r0, c1r1);  // col c0+1: rows r, r+1
            const int r = r0 + 2*p;
            if (MODE == 0){
                *(float2*)(dst + r*SX + c0)     = make_float2(a0, c1r0);
                *(float2*)(dst + (r+1)*SX + c0) = make_float2(a1, c1r1);
            } else if (MODE == 1){
                float2* d0 = (float2*)(dst + r*SX + c0);
                float2* d1 = (float2*)(dst + (r+1)*SX + c0);
                float2 x0 = *d0, x1 = *d1;
                x0.x += a0; x0.y += c1r0; *d0 = x0;
                x1.x += a1; x1.y += c1r1; *d1 = x1;
            } else { // gelu, transposed store for the w2 pass
                dst[c0*STR + r]       = gelu_tanh(a0);
                dst[c0*STR + r + 1]   = gelu_tanh(a1);
                dst[(c0+1)*STR + r]   = gelu_tanh(c1r0);
                dst[(c0+1)*STR + r+1] = gelu_tanh(c1r1);
            }
        }
    }
}

// ---- attention: thread = (head,row); f32x2 dots; skips dead rows & dead keys.
// Output written TRANSPOSED into HT (src for the wo GEMM).
__device__ __forceinline__ void attention_t(const float* __restrict__ Qb,
        const float* __restrict__ Kb, const float* __restrict__ Vb,
        float* __restrict__ HTo, int valid)
{
    const int t    = threadIdx.x;
    const int head = t >> 6;
    const int row  = t & 63;
    const int base = head * DHn;
    const float scale = 0.17677669529663687f; // 1/sqrt(32)

    if (row < valid){
        ull qp[16];
        const ull* qpt = (const ull*)(Qb + row*SX + base);
        #pragma unroll
        for (int j = 0; j < 16; j++) qp[j] = qpt[j];

        float s[64];
        #pragma unroll
        for (int tt = 0; tt < 64; ++tt){
            if (tt < valid){
                const ull* kpt = (const ull*)(Kb + tt*SX + base);
                ull acc2 = pk2(0.f, 0.f);
                #pragma unroll
                for (int j = 0; j < 16; j++) acc2 = fma2(qp[j], kpt[j], acc2);
                float lo, hi; upk2(acc2, lo, hi);
                s[tt] = (lo + hi) * scale;
            } else s[tt] = 0.f;
        }
        float m = -1e30f;
        #pragma unroll
        for (int tt = 0; tt < 64; ++tt) if (tt < valid) m = fmaxf(m, s[tt]);
        float sum = 0.f;
        #pragma unroll
        for (int tt = 0; tt < 64; ++tt){
            if (tt < valid){ float e = __expf(s[tt] - m); s[tt] = e; sum += e; }
        }
        ull op[16];
        #pragma unroll
        for (int j = 0; j < 16; j++) op[j] = pk2(0.f, 0.f);
        #pragma unroll
        for (int tt = 0; tt < 64; ++tt){
            if (tt < valid){
                const ull ad = pk2(s[tt], s[tt]);
                const ull* vpt = (const ull*)(Vb + tt*SX + base);
                #pragma unroll
                for (int j = 0; j < 16; j++) op[j] = fma2(ad, vpt[j], op[j]);
            }
        }
        const float inv = 1.0f / sum;
        #pragma unroll
        for (int j = 0; j < 16; j++){
            float lo, hi; upk2(op[j], lo, hi);
            HTo[(base + 2*j)*STR + row]     = lo * inv;
            HTo[(base + 2*j + 1)*STR + row] = hi * inv;
        }
    }
}

#define SMEM_FLOATS (Sn*SX /*X*/ + En*STR /*HT*/ + 3*Sn*SX /*QKV*/ + 2*Sn*16 /*rope*/)
#define SMEM_BYTES  (SMEM_FLOATS*4)

__global__ void __launch_bounds__(NTHREADS, 1) rowinteraction_kernel(
    const float* __restrict__ emb,  const float* __restrict__ cls,
    const float* __restrict__ ln1g, const float* __restrict__ ln1b,
    const float* __restrict__ wq,   const float* __restrict__ bq,
    const float* __restrict__ wk,   const float* __restrict__ bk,
    const float* __restrict__ wv,   const float* __restrict__ bv,
    const float* __restrict__ wo,   const float* __restrict__ bo,
    const float* __restrict__ ln2g, const float* __restrict__ ln2b,
    const float* __restrict__ w1,   const float* __restrict__ b1,
    const float* __restrict__ w2,   const float* __restrict__ b2,
    const float* __restrict__ og,   const float* __restrict__ ob,
    const int*   __restrict__ dvec, float* __restrict__ out)
{
    extern __shared__ float smf[];
    float* X   = smf;                 // [64][132] residual stream (row-major)
    float* HT  = X  + Sn*SX;          // [128][66] transposed activations (GEMM src)
    float* Qb  = HT + En*STR;         // [64][132] row-major
    float* Kb  = Qb + Sn*SX;
    float* Vb  = Kb + Sn*SX;
    float* FFT = Qb;                  // [256][66] transposed FF acts, overlays Q+K (16896 fl)
    float* RC  = Vb + Sn*SX;          // rope cos [64][16]
    float* RS  = RC + Sn*16;          // rope sin

    const int tid   = threadIdx.x;
    const int n     = blockIdx.x;
    const int bidx  = n >> 10;        // T = 1024
    const int valid = dvec[bidx] + Cn;          // 4..63
    const int nrb   = (valid + 7) >> 3;         // live 8-row blocks, 1..8

    for (int idx = tid; idx < Sn*16; idx += NTHREADS){
        int pos = idx >> 4, f = idx & 15;
        float inv = expf(-((float)(2*f) / (float)DHn) * logf(100000.0f));
        float ang = (float)pos * inv;
        RC[idx] = cosf(ang); RS[idx] = sinf(ang);
    }
    for (int idx = tid; idx < Sn*En; idx += NTHREADS){
        int r = idx >> 7, c = idx & 127;
        float v = (r < Cn) ? cls[r*En + c] : emb[((size_t)n*Sn + r)*En + c];
        X[r*SX + c] = v;
    }
    __syncthreads();

    for (int l = 0; l < Ln; ++l){
        layernorm_t(X, HT, ln1g + l*En, ln1b + l*En, valid);
        __syncthreads();
        gemm_t<En, En, 0>(HT, wq + l*En*En, bq + l*En, Qb, nrb);
        gemm_t<En, En, 0>(HT, wk + l*En*En, bk + l*En, Kb, nrb);
        gemm_t<En, En, 0>(HT, wv + l*En*En, bv + l*En, Vb, nrb);
        __syncthreads();
        // RoPE in place on live rows
        for (int idx = tid; idx < Sn*NHn*16; idx += NTHREADS){
            int row = idx >> 6;
            if (row < valid){
                int hj = idx & 63; int h = hj >> 4; int j = hj & 15;
                float cc = RC[row*16 + j], ss = RS[row*16 + j];
                int o1 = row*SX + h*DHn + j, o2 = o1 + 16;
                float q1 = Qb[o1], q2 = Qb[o2];
                Qb[o1] = q1*cc - q2*ss;  Qb[o2] = q2*cc + q1*ss;
                float k1 = Kb[o1], k2 = Kb[o2];
                Kb[o1] = k1*cc - k2*ss;  Kb[o2] = k2*cc + k1*ss;
            }
        }
        __syncthreads();
        attention_t(Qb, Kb, Vb, HT, valid);
        __syncthreads();
        gemm_t<En, En, 1>(HT, wo + l*En*En, bo + l*En, X, nrb);     // x += o@wo+bo
        __syncthreads();
        layernorm_t(X, HT, ln2g + l*En, ln2b + l*En, valid);
        __syncthreads();
        gemm_t<En, FFn, 2>(HT, w1 + l*En*FFn, b1 + l*FFn, FFT, nrb); // gelu -> FFT (transposed)
        __syncthreads();
        gemm_t<FFn, En, 1>(FFT, w2 + l*FFn*En, b2 + l*En, X, nrb);   // x += ff@w2+b2
        __syncthreads();
    }

    // Epilogue: out-layernorm rows 0..3, write (B,T,C*E)
    const int warp = tid >> 5, lane = tid & 31;
    if (warp < Cn){
        const float4 xv = *(const float4*)(X + warp*SX + lane*4);
        float s  = xv.x + xv.y + xv.z + xv.w;
        float s2 = xv.x*xv.x + xv.y*xv.y + xv.z*xv.z + xv.w*xv.w;
        #pragma unroll
        for (int o = 16; o; o >>= 1){
            s  += __shfl_xor_sync(0xffffffffu, s,  o);
            s2 += __shfl_xor_sync(0xffffffffu, s2, o);
        }
        const float m    = s * 0.0078125f;
        const float rstd = rsqrtf(s2*0.0078125f - m*m + 1e-5f);
        const float4 gv  = *(const float4*)(og + lane*4);
        const float4 bv4 = *(const float4*)(ob + lane*4);
        float4 ovv;
        ovv.x = (xv.x - m)*rstd*gv.x + bv4.x;
        ovv.y = (xv.y - m)*rstd*gv.y + bv4.y;
        ovv.z = (xv.z - m)*rstd*gv.z + bv4.z;
        ovv.w = (xv.w - m)*rstd*gv.w + bv4.w;
        *(float4*)(out + (size_t)n*(Cn*En) + warp*En + lane*4) = ovv;
    }
}

extern "C" void kernel_launch(void* const* d_in, const int* in_sizes, int n_in,
                              void* d_out, int out_size)
{
    (void)in_sizes; (void)n_in; (void)out_size;
    cudaFuncSetAttribute(rowinteraction_kernel,
                         cudaFuncAttributeMaxDynamicSharedMemorySize, SMEM_BYTES);
    rowinteraction_kernel<<<Bn*Tn, NTHREADS, SMEM_BYTES>>>(
        (const float*)d_in[0],  (const float*)d_in[1],
        (const float*)d_in[2],  (const float*)d_in[3],
        (const float*)d_in[4],  (const float*)d_in[5],
        (const float*)d_in[6],  (const float*)d_in[7],
        (const float*)d_in[8],  (const float*)d_in[9],
        (const float*)d_in[10], (const float*)d_in[11],
        (const float*)d_in[12], (const float*)d_in[13],
        (const float*)d_in[14], (const float*)d_in[15],
        (const float*)d_in[16], (const float*)d_in[17],
        (const float*)d_in[18], (const float*)d_in[19],
        (const int*)d_in[20],   (float*)d_out);
}